// round 1
// baseline (speedup 1.0000x reference)
#include <cuda_runtime.h>
#include <cmath>

#define N_TOK 4096
#define E_DIM 512
#define NH 8
#define DK 64
#define WSZ 128
#define NBLK 32          // 4096 / 128
#define NDIMS 16
#define QKV_LD 1536
#define CHUNKS 32        // cema chunks of 128 steps

// ---------------- scratch (device globals: no allocation allowed) -------------
__device__ float g_qkv [N_TOK * QKV_LD];     // 25 MB
__device__ float g_attn[N_TOK * E_DIM];      // 8 MB
__device__ float g_cema[N_TOK * E_DIM];      // 8 MB
__device__ float g_hend [CHUNKS * E_DIM * NDIMS];
__device__ float g_carry[CHUNKS * E_DIM * NDIMS];
__device__ float g_sv[E_DIM];

// ---------------- generic 128x128 SGEMM, 256 thr, 8x8 microtile ---------------
// C[M,N] = A[M,K] @ B[K,N] + bias   (mode 0)
// C      = w0*(A@B + bias) + w1*cema, w = softmax(aw)   (mode 1)
__global__ void __launch_bounds__(256)
sgemm_kernel(const float* __restrict__ A, const float* __restrict__ B,
             const float* __restrict__ bias, float* __restrict__ C,
             int M, int N, int K, int mode,
             const float* __restrict__ cema, const float* __restrict__ aw)
{
    __shared__ float As[8][128];
    __shared__ float Bs[8][128];
    const int tid = threadIdx.x;
    const int m0 = blockIdx.y * 128, n0 = blockIdx.x * 128;
    const int tx = tid & 15, ty = tid >> 4;
    const int arow = tid >> 1,  acol = (tid & 1) << 2;   // A tile 128x8
    const int brow = tid >> 5,  bcol = (tid & 31) << 2;  // B tile 8x128

    const float* Ap = A + (m0 + arow) * K + acol;
    const float* Bp = B + brow * N + n0 + bcol;

    float acc[8][8];
#pragma unroll
    for (int r = 0; r < 8; r++)
#pragma unroll
        for (int c = 0; c < 8; c++) acc[r][c] = 0.f;

    for (int k0 = 0; k0 < K; k0 += 8) {
        float4 a  = *(const float4*)Ap;  Ap += 8;
        float4 bv = *(const float4*)Bp;  Bp += 8 * N;
        As[acol + 0][arow] = a.x;
        As[acol + 1][arow] = a.y;
        As[acol + 2][arow] = a.z;
        As[acol + 3][arow] = a.w;
        *(float4*)&Bs[brow][bcol] = bv;
        __syncthreads();
#pragma unroll
        for (int k = 0; k < 8; k++) {
            float ar[8], br[8];
            *(float4*)&ar[0] = *(const float4*)&As[k][ty * 8];
            *(float4*)&ar[4] = *(const float4*)&As[k][ty * 8 + 4];
            *(float4*)&br[0] = *(const float4*)&Bs[k][tx * 8];
            *(float4*)&br[4] = *(const float4*)&Bs[k][tx * 8 + 4];
#pragma unroll
            for (int r = 0; r < 8; r++)
#pragma unroll
                for (int c = 0; c < 8; c++)
                    acc[r][c] = fmaf(ar[r], br[c], acc[r][c]);
        }
        __syncthreads();
    }

    float w0 = 1.f, w1 = 0.f;
    if (mode == 1) {
        float a0 = aw[0], a1 = aw[1];
        float mx = fmaxf(a0, a1);
        float e0 = expf(a0 - mx), e1 = expf(a1 - mx);
        float inv = 1.f / (e0 + e1);
        w0 = e0 * inv; w1 = e1 * inv;
    }

#pragma unroll
    for (int r = 0; r < 8; r++) {
        const int m = m0 + ty * 8 + r;
#pragma unroll
        for (int c = 0; c < 8; c += 4) {
            const int n = n0 + tx * 8 + c;
            float4 o;
            o.x = acc[r][c + 0] + bias[n + 0];
            o.y = acc[r][c + 1] + bias[n + 1];
            o.z = acc[r][c + 2] + bias[n + 2];
            o.w = acc[r][c + 3] + bias[n + 3];
            if (mode == 1) {
                float4 cm = *(const float4*)&cema[m * N + n];
                o.x = fmaf(w0, o.x, w1 * cm.x);
                o.y = fmaf(w0, o.y, w1 * cm.y);
                o.z = fmaf(w0, o.z, w1 * cm.z);
                o.w = fmaf(w0, o.w, w1 * cm.w);
            }
            *(float4*)&C[m * N + n] = o;
        }
    }
}

// ---------------- per-head V column sums ----------------
__global__ void sv_init_kernel() { g_sv[threadIdx.x] = 0.f; }

__global__ void sv_kernel()
{
    const int c  = threadIdx.x;           // 0..511 (h*64+d)
    const int t0 = blockIdx.x * 128;
    float s = 0.f;
#pragma unroll 4
    for (int t = t0; t < t0 + 128; t++)
        s += g_qkv[t * QKV_LD + 2 * E_DIM + c];
    atomicAdd(&g_sv[c], s);
}

// ---------------- fused block-local attention -----------------
// grid: NH*NBLK blocks, 256 threads. Dynamic smem:
//   qv  [64][128]  (q d-major; reused as v [128][64])
//   ks  [64][128]
//   Est [128][132] (E' transposed: [j][i], pad 132 for banks + f4 align)
//   rowinv[128]
#define EST_LD 132
#define ATTN_SMEM_FLOATS (8192 + 8192 + 128 * EST_LD + 128)

__global__ void __launch_bounds__(256)
attn_kernel()
{
    extern __shared__ float sm[];
    float* qv     = sm;
    float* ks     = sm + 8192;
    float* Est    = sm + 16384;
    float* rowinv = sm + 16384 + 128 * EST_LD;

    const int tid = threadIdx.x;
    const int h   = blockIdx.x >> 5;
    const int blk = blockIdx.x & 31;
    const int t0  = blk * WSZ;
    const int coff = h * DK;

    // load Q,K tiles (transposed to d-major)
    for (int idx = tid; idx < 2048; idx += 256) {
        const int i = idx >> 4, d4 = (idx & 15) << 2;
        const float* src = &g_qkv[(t0 + i) * QKV_LD + coff + d4];
        float4 q4 = *(const float4*)src;
        float4 k4 = *(const float4*)(src + E_DIM);
        qv[(d4 + 0) * 128 + i] = q4.x;  ks[(d4 + 0) * 128 + i] = k4.x;
        qv[(d4 + 1) * 128 + i] = q4.y;  ks[(d4 + 1) * 128 + i] = k4.y;
        qv[(d4 + 2) * 128 + i] = q4.z;  ks[(d4 + 2) * 128 + i] = k4.z;
        qv[(d4 + 3) * 128 + i] = q4.w;  ks[(d4 + 3) * 128 + i] = k4.w;
    }
    __syncthreads();

    // S = Q K^T : thread (tx->i, ty->j), 8x8
    const int tx = tid & 15, ty = tid >> 4;
    const int ib = tx * 8, jb = ty * 8;
    float accS[8][8];
#pragma unroll
    for (int r = 0; r < 8; r++)
#pragma unroll
        for (int c = 0; c < 8; c++) accS[r][c] = 0.f;

#pragma unroll 4
    for (int d = 0; d < 64; d++) {
        float qr[8], kr[8];
        *(float4*)&qr[0] = *(const float4*)&qv[d * 128 + ib];
        *(float4*)&qr[4] = *(const float4*)&qv[d * 128 + ib + 4];
        *(float4*)&kr[0] = *(const float4*)&ks[d * 128 + jb];
        *(float4*)&kr[4] = *(const float4*)&ks[d * 128 + jb + 4];
#pragma unroll
        for (int r = 0; r < 8; r++)
#pragma unroll
            for (int c = 0; c < 8; c++)
                accS[r][c] = fmaf(qr[r], kr[c], accS[r][c]);
    }

    // E' = exp(s/8)-1 on causal-in-block, else 0; store transposed Est[j][i]
#pragma unroll
    for (int c = 0; c < 8; c++) {
        const int j = jb + c;
        float e[8];
#pragma unroll
        for (int r = 0; r < 8; r++) {
            const int i = ib + r;
            e[r] = (j <= i) ? (expf(accS[r][c] * 0.125f) - 1.0f) : 0.0f;
        }
        *(float4*)&Est[j * EST_LD + ib]     = make_float4(e[0], e[1], e[2], e[3]);
        *(float4*)&Est[j * EST_LD + ib + 4] = make_float4(e[4], e[5], e[6], e[7]);
    }
    __syncthreads();

    // row normalizers: Z_i = rowsum(E') + 4096
    if (tid < 128) {
        float s = 0.f;
#pragma unroll 4
        for (int j = 0; j < 128; j++) s += Est[j * EST_LD + tid];
        rowinv[tid] = 1.0f / (s + 4096.0f);
    }

    // load V into qv region as [j][64]
    for (int idx = tid; idx < 2048; idx += 256) {
        const int j = idx >> 4, d4 = (idx & 15) << 2;
        float4 vv = *(const float4*)&g_qkv[(t0 + j) * QKV_LD + 2 * E_DIM + coff + d4];
        *(float4*)&qv[j * 64 + d4] = vv;
    }
    __syncthreads();

    // O = E' @ V : thread (ty->i 8, tx->d 4)
    const int i0 = ty * 8, d0 = tx * 4;
    float accO[8][4];
#pragma unroll
    for (int r = 0; r < 8; r++)
#pragma unroll
        for (int c = 0; c < 4; c++) accO[r][c] = 0.f;

#pragma unroll 2
    for (int j = 0; j < 128; j++) {
        float er[8];
        *(float4*)&er[0] = *(const float4*)&Est[j * EST_LD + i0];
        *(float4*)&er[4] = *(const float4*)&Est[j * EST_LD + i0 + 4];
        float4 vv = *(const float4*)&qv[j * 64 + d0];
#pragma unroll
        for (int r = 0; r < 8; r++) {
            accO[r][0] = fmaf(er[r], vv.x, accO[r][0]);
            accO[r][1] = fmaf(er[r], vv.y, accO[r][1]);
            accO[r][2] = fmaf(er[r], vv.z, accO[r][2]);
            accO[r][3] = fmaf(er[r], vv.w, accO[r][3]);
        }
    }

    const float4 sv4 = *(const float4*)&g_sv[coff + d0];
#pragma unroll
    for (int r = 0; r < 8; r++) {
        const int i = i0 + r;
        const float riv = rowinv[i];
        float4 o;
        o.x = (accO[r][0] + sv4.x) * riv;
        o.y = (accO[r][1] + sv4.y) * riv;
        o.z = (accO[r][2] + sv4.z) * riv;
        o.w = (accO[r][3] + sv4.w) * riv;
        *(float4*)&g_attn[(t0 + i) * E_DIM + coff + d0] = o;
    }
}

// ---------------- CEMA: chunked linear scan --------------------
// pass1: per (e, chunk) local scan with h0=0; y_local -> g_cema, h_end -> g_hend
__global__ void __launch_bounds__(128)
cema_pass1(const float* __restrict__ x, const float* __restrict__ p_coeff,
           const float* __restrict__ q_coeff, const float* __restrict__ gamma)
{
    const int gid  = blockIdx.x * 128 + threadIdx.x;   // 0..16383
    const int e    = gid & 511;
    const int chnk = gid >> 9;
    float p[NDIMS], q[NDIMS], g[NDIMS], h[NDIMS];
#pragma unroll
    for (int d = 0; d < NDIMS; d++) {
        p[d] = p_coeff[e * NDIMS + d];
        q[d] = q_coeff[e * NDIMS + d];
        g[d] = gamma  [e * NDIMS + d];
        h[d] = 0.f;
    }
    const int tbase = chnk * 128;
    for (int t = 0; t < 128; t++) {
        const float xv = x[(tbase + t) * E_DIM + e];
        float y = 0.f;
#pragma unroll
        for (int d = 0; d < NDIMS; d++) {
            h[d] = fmaf(q[d], h[d], p[d] * xv);
            y    = fmaf(g[d], h[d], y);
        }
        g_cema[(tbase + t) * E_DIM + e] = y;
    }
#pragma unroll
    for (int d = 0; d < NDIMS; d++)
        g_hend[chnk * (E_DIM * NDIMS) + e * NDIMS + d] = h[d];
}

// pass B: carry scan across chunks: G_c = hend_c + q^128 * G_{c-1}
__global__ void __launch_bounds__(128)
cema_carry(const float* __restrict__ q_coeff)
{
    const int gid = blockIdx.x * 128 + threadIdx.x;    // 0..8191 == e*16+d
    const float q = q_coeff[gid];
    float q128 = q;
#pragma unroll
    for (int i = 0; i < 7; i++) q128 *= q128;          // q^128
    float G = 0.f;
    for (int c = 0; c < CHUNKS; c++) {
        g_carry[c * (E_DIM * NDIMS) + gid] = G;        // carry INTO chunk c
        G = fmaf(q128, G, g_hend[c * (E_DIM * NDIMS) + gid]);
    }
}

// pass2: y_t += sum_d gamma_d * q_d^{t_local+1} * carry_d
__global__ void __launch_bounds__(128)
cema_pass2(const float* __restrict__ q_coeff, const float* __restrict__ gamma)
{
    const int gid  = blockIdx.x * 128 + threadIdx.x;
    const int e    = gid & 511;
    const int chnk = gid >> 9;
    if (chnk == 0) return;                              // zero carry
    float q[NDIMS], w[NDIMS];
#pragma unroll
    for (int d = 0; d < NDIMS; d++) {
        q[d] = q_coeff[e * NDIMS + d];
        w[d] = gamma[e * NDIMS + d] * g_carry[chnk * (E_DIM * NDIMS) + e * NDIMS + d];
    }
    const int tbase = chnk * 128;
    for (int t = 0; t < 128; t++) {
        float y = 0.f;
#pragma unroll
        for (int d = 0; d < NDIMS; d++) {
            w[d] *= q[d];
            y    += w[d];
        }
        g_cema[(tbase + t) * E_DIM + e] += y;
    }
}

// ---------------------------- launch ----------------------------
extern "C" void kernel_launch(void* const* d_in, const int* in_sizes, int n_in,
                              void* d_out, int out_size)
{
    (void)in_sizes; (void)n_in; (void)out_size;
    const float* x       = (const float*)d_in[0];
    const float* W_qkv   = (const float*)d_in[1];
    const float* b_qkv   = (const float*)d_in[2];
    const float* W_out   = (const float*)d_in[3];
    const float* b_out   = (const float*)d_in[4];
    // d_in[5] = omega (unused by reference)
    const float* p_coeff = (const float*)d_in[6];
    const float* q_coeff = (const float*)d_in[7];
    const float* gamma   = (const float*)d_in[8];
    const float* aw      = (const float*)d_in[9];
    float* out = (float*)d_out;

    float *qkvp = nullptr, *attnp = nullptr, *cemap = nullptr;
    cudaGetSymbolAddress((void**)&qkvp,  g_qkv);
    cudaGetSymbolAddress((void**)&attnp, g_attn);
    cudaGetSymbolAddress((void**)&cemap, g_cema);

    cudaFuncSetAttribute(attn_kernel, cudaFuncAttributeMaxDynamicSharedMemorySize,
                         ATTN_SMEM_FLOATS * (int)sizeof(float));

    // QKV projection: (4096 x 512) @ (512 x 1536) + b
    sgemm_kernel<<<dim3(QKV_LD / 128, N_TOK / 128), 256>>>(
        x, W_qkv, b_qkv, qkvp, N_TOK, QKV_LD, E_DIM, 0, nullptr, nullptr);

    // per-head V sums
    sv_init_kernel<<<1, E_DIM>>>();
    sv_kernel<<<NBLK, E_DIM>>>();

    // block-local attention
    attn_kernel<<<NH * NBLK, 256, ATTN_SMEM_FLOATS * (int)sizeof(float)>>>();

    // CEMA (independent of attention; sequential stream order is fine)
    cema_pass1<<<(E_DIM * CHUNKS) / 128, 128>>>(x, p_coeff, q_coeff, gamma);
    cema_carry<<<(E_DIM * NDIMS) / 128, 128>>>(q_coeff);
    cema_pass2<<<(E_DIM * CHUNKS) / 128, 128>>>(q_coeff, gamma);

    // out projection fused with adaptive combine
    sgemm_kernel<<<dim3(E_DIM / 128, N_TOK / 128), 256>>>(
        attnp, W_out, b_out, out, N_TOK, E_DIM, E_DIM, 1, cemap, aw);
}

// round 3
// speedup vs baseline: 1.7689x; 1.7689x over previous
#include <cuda_runtime.h>
#include <cuda_bf16.h>
#include <cmath>
#include <cstdint>

#define N_TOK 4096
#define E_DIM 512
#define NH 8
#define DK 64
#define WSZ 128
#define NBLK 32
#define NDIMS 16
#define QKV_LD 1536
#define CHUNKS 32
#define KDIM 512

// ---------------- scratch (device globals) ----------------
__device__ float g_qkv [N_TOK * QKV_LD];
__device__ float g_cema[N_TOK * E_DIM];
__device__ float g_hend [CHUNKS * E_DIM * NDIMS];
__device__ float g_carry[CHUNKS * E_DIM * NDIMS];
__device__ float g_sv[E_DIM];
__device__ __nv_bfloat16 g_xhi [N_TOK * E_DIM];
__device__ __nv_bfloat16 g_xlo [N_TOK * E_DIM];
__device__ __nv_bfloat16 g_ahi [N_TOK * E_DIM];
__device__ __nv_bfloat16 g_alo [N_TOK * E_DIM];
__device__ __nv_bfloat16 g_wqT_hi[QKV_LD * E_DIM];
__device__ __nv_bfloat16 g_wqT_lo[QKV_LD * E_DIM];
__device__ __nv_bfloat16 g_woT_hi[E_DIM * E_DIM];
__device__ __nv_bfloat16 g_woT_lo[E_DIM * E_DIM];

// ---------------- PTX helpers ----------------
__device__ __forceinline__ uint32_t smem_u32(const void* p) {
    uint32_t a;
    asm("{ .reg .u64 t; cvta.to.shared.u64 t, %1; cvt.u32.u64 %0, t; }" : "=r"(a) : "l"(p));
    return a;
}
__device__ __forceinline__ void ldsm_x4(uint32_t* r, uint32_t addr) {
    asm volatile("ldmatrix.sync.aligned.m8n8.x4.shared.b16 {%0,%1,%2,%3}, [%4];"
        : "=r"(r[0]), "=r"(r[1]), "=r"(r[2]), "=r"(r[3]) : "r"(addr));
}
__device__ __forceinline__ void ldsm_x2(uint32_t* r, uint32_t addr) {
    asm volatile("ldmatrix.sync.aligned.m8n8.x2.shared.b16 {%0,%1}, [%2];"
        : "=r"(r[0]), "=r"(r[1]) : "r"(addr));
}
__device__ __forceinline__ void mma_bf16(float* d, const uint32_t* a, const uint32_t* b) {
    asm volatile("mma.sync.aligned.m16n8k16.row.col.f32.bf16.bf16.f32 "
        "{%0,%1,%2,%3}, {%4,%5,%6,%7}, {%8,%9}, {%0,%1,%2,%3};"
        : "+f"(d[0]), "+f"(d[1]), "+f"(d[2]), "+f"(d[3])
        : "r"(a[0]), "r"(a[1]), "r"(a[2]), "r"(a[3]), "r"(b[0]), "r"(b[1]));
}

// ---------------- prep kernels ----------------
__global__ void conv_hilo(const float* __restrict__ X,
                          __nv_bfloat16* __restrict__ hi, __nv_bfloat16* __restrict__ lo)
{
    const int i = blockIdx.x * blockDim.x + threadIdx.x;   // per float4
    float4 v = ((const float4*)X)[i];
    __nv_bfloat16 hx = __float2bfloat16(v.x), hy = __float2bfloat16(v.y);
    __nv_bfloat16 hz = __float2bfloat16(v.z), hw = __float2bfloat16(v.w);
    __nv_bfloat162* H = (__nv_bfloat162*)hi;
    __nv_bfloat162* L = (__nv_bfloat162*)lo;
    H[i * 2 + 0] = __nv_bfloat162{hx, hy};
    H[i * 2 + 1] = __nv_bfloat162{hz, hw};
    L[i * 2 + 0] = __nv_bfloat162{__float2bfloat16(v.x - __bfloat162float(hx)),
                                  __float2bfloat16(v.y - __bfloat162float(hy))};
    L[i * 2 + 1] = __nv_bfloat162{__float2bfloat16(v.z - __bfloat162float(hz)),
                                  __float2bfloat16(v.w - __bfloat162float(hw))};
}

// W [Kdim x Ndim] fp32 -> WT [Ndim x Kdim] bf16 hi/lo
__global__ void transpose_conv(const float* __restrict__ W,
                               __nv_bfloat16* __restrict__ Thi, __nv_bfloat16* __restrict__ Tlo,
                               int Kdim, int Ndim)
{
    __shared__ float t[32][33];
    const int n0 = blockIdx.x * 32, k0 = blockIdx.y * 32;
    const int tx = threadIdx.x, ty = threadIdx.y;
#pragma unroll
    for (int s = 0; s < 32; s += 8)
        t[ty + s][tx] = W[(k0 + ty + s) * Ndim + n0 + tx];
    __syncthreads();
#pragma unroll
    for (int s = 0; s < 32; s += 8) {
        float v = t[tx][ty + s];
        __nv_bfloat16 h = __float2bfloat16(v);
        Thi[(n0 + ty + s) * Kdim + k0 + tx] = h;
        Tlo[(n0 + ty + s) * Kdim + k0 + tx] = __float2bfloat16(v - __bfloat162float(h));
    }
}

// ---------------- bf16x3 tensor-core GEMM (mma.sync) ----------------
// C[128x128] tile/CTA. A:[M x 512] bf16 hi/lo row-major. B:[N x 512] bf16 hi/lo (K-major).
// 8 warps: 2(m) x 4(n), warp tile 64x32 via m16n8k16.
// mode 0: C = acc + bias ; mode 1: C = w0*(acc+bias) + w1*cema
#define LDSB 144              // smem row stride in bytes (72 bf16)
#define A_HI_OFF 0
#define A_LO_OFF 18432
#define B_HI_OFF 36864
#define B_LO_OFF 55296
#define GEMM_SMEM_BYTES 73728

__global__ void __launch_bounds__(256, 2)
gemm_mma(const __nv_bfloat16* __restrict__ Ahi, const __nv_bfloat16* __restrict__ Alo,
         const __nv_bfloat16* __restrict__ Bhi, const __nv_bfloat16* __restrict__ Blo,
         const float* __restrict__ bias, float* __restrict__ C, int ldc, int mode,
         const float* __restrict__ cema, const float* __restrict__ aw)
{
    extern __shared__ __align__(16) char smem[];
    const uint32_t sb = smem_u32(smem);
    const int tid = threadIdx.x;
    const int wid = tid >> 5, lane = tid & 31;
    const int wm = wid & 1, wn = wid >> 1;            // warp grid 2 x 4
    const int m0 = blockIdx.y * 128, n0 = blockIdx.x * 128;

    // ldmatrix per-lane smem offsets (bytes)
    const uint32_t a_off = (uint32_t)(wm * 64 + (lane & 15)) * LDSB + ((lane >> 4) << 4);
    const uint32_t b_off = (uint32_t)(wn * 32 + (lane & 7))  * LDSB + (((lane >> 3) & 1) << 4);

    float acc[4][4][4];
#pragma unroll
    for (int mt = 0; mt < 4; mt++)
#pragma unroll
        for (int nt = 0; nt < 4; nt++)
#pragma unroll
            for (int c = 0; c < 4; c++) acc[mt][nt][c] = 0.f;

    for (int ch = 0; ch < 8; ch++) {
        const int kb = ch * 64;
        // load A/B hi/lo tiles: 128 rows x 64 bf16 each
#pragma unroll
        for (int it = 0; it < 4; it++) {
            const int idx = tid + it * 256;
            const int r = idx >> 3, seg = idx & 7;
            const int so = r * LDSB + seg * 16;
            const int ga = (m0 + r) * KDIM + kb + seg * 8;
            const int gb = (n0 + r) * KDIM + kb + seg * 8;
            *(uint4*)(smem + A_HI_OFF + so) = *(const uint4*)&Ahi[ga];
            *(uint4*)(smem + A_LO_OFF + so) = *(const uint4*)&Alo[ga];
            *(uint4*)(smem + B_HI_OFF + so) = *(const uint4*)&Bhi[gb];
            *(uint4*)(smem + B_LO_OFF + so) = *(const uint4*)&Blo[gb];
        }
        __syncthreads();

#pragma unroll
        for (int ks = 0; ks < 4; ks++) {
            const uint32_t kofs = ks * 32;  // 16 bf16 = 32 bytes
            uint32_t bh[4][2], bl[4][2];
#pragma unroll
            for (int nt = 0; nt < 4; nt++) {
                ldsm_x2(bh[nt], sb + B_HI_OFF + b_off + nt * (8 * LDSB) + kofs);
                ldsm_x2(bl[nt], sb + B_LO_OFF + b_off + nt * (8 * LDSB) + kofs);
            }
#pragma unroll
            for (int mt = 0; mt < 4; mt++) {
                uint32_t ah[4], al[4];
                ldsm_x4(ah, sb + A_HI_OFF + a_off + mt * (16 * LDSB) + kofs);
                ldsm_x4(al, sb + A_LO_OFF + a_off + mt * (16 * LDSB) + kofs);
#pragma unroll
                for (int nt = 0; nt < 4; nt++) {
                    mma_bf16(acc[mt][nt], ah, bh[nt]);
                    mma_bf16(acc[mt][nt], ah, bl[nt]);
                    mma_bf16(acc[mt][nt], al, bh[nt]);
                }
            }
        }
        __syncthreads();
    }

    float w0 = 1.f, w1 = 0.f;
    if (mode == 1) {
        float a0 = aw[0], a1 = aw[1];
        float mx = fmaxf(a0, a1);
        float e0 = expf(a0 - mx), e1 = expf(a1 - mx);
        float inv = 1.f / (e0 + e1);
        w0 = e0 * inv; w1 = e1 * inv;
    }

    // epilogue: c0,c1 -> row (lane>>2), cols (lane&3)*2; c2,c3 -> row+8
#pragma unroll
    for (int mt = 0; mt < 4; mt++) {
        const int r0 = m0 + wm * 64 + mt * 16 + (lane >> 2);
#pragma unroll
        for (int nt = 0; nt < 4; nt++) {
            const int col = n0 + wn * 32 + nt * 8 + (lane & 3) * 2;
            const float b0v = bias[col], b1v = bias[col + 1];
            float2 v0 = make_float2(acc[mt][nt][0] + b0v, acc[mt][nt][1] + b1v);
            float2 v1 = make_float2(acc[mt][nt][2] + b0v, acc[mt][nt][3] + b1v);
            if (mode == 1) {
                float2 c0 = *(const float2*)&cema[r0 * ldc + col];
                float2 c1 = *(const float2*)&cema[(r0 + 8) * ldc + col];
                v0.x = fmaf(w0, v0.x, w1 * c0.x);  v0.y = fmaf(w0, v0.y, w1 * c0.y);
                v1.x = fmaf(w0, v1.x, w1 * c1.x);  v1.y = fmaf(w0, v1.y, w1 * c1.y);
            }
            *(float2*)&C[r0 * ldc + col]       = v0;
            *(float2*)&C[(r0 + 8) * ldc + col] = v1;
        }
    }
}

// ---------------- per-head V column sums ----------------
__global__ void sv_init_kernel() { g_sv[threadIdx.x] = 0.f; }

__global__ void sv_kernel()
{
    const int c  = threadIdx.x;
    const int t0 = blockIdx.x * 128;
    float s = 0.f;
#pragma unroll 4
    for (int t = t0; t < t0 + 128; t++)
        s += g_qkv[t * QKV_LD + 2 * E_DIM + c];
    atomicAdd(&g_sv[c], s);
}

// ---------------- fused block-local attention ----------------
#define ATTN_SMEM_FLOATS (16384 + 8192 + 128)

__global__ void __launch_bounds__(256)
attn_kernel()
{
    extern __shared__ float sm[];
    float* qv     = sm;
    float* ks     = sm + 8192;
    float* Est    = sm;              // overlaps q/k after S is in registers
    float* vv     = sm + 16384;
    float* rowinv = sm + 16384 + 8192;

    const int tid = threadIdx.x;
    const int h   = blockIdx.x >> 5;
    const int blk = blockIdx.x & 31;
    const int t0  = blk * WSZ;
    const int coff = h * DK;

    for (int idx = tid; idx < 2048; idx += 256) {
        const int i = idx >> 4, d4 = (idx & 15) << 2;
        const float* src = &g_qkv[(t0 + i) * QKV_LD + coff + d4];
        float4 q4 = *(const float4*)src;
        float4 k4 = *(const float4*)(src + E_DIM);
        float4 v4 = *(const float4*)(src + 2 * E_DIM);
        qv[(d4 + 0) * 128 + i] = q4.x;  ks[(d4 + 0) * 128 + i] = k4.x;
        qv[(d4 + 1) * 128 + i] = q4.y;  ks[(d4 + 1) * 128 + i] = k4.y;
        qv[(d4 + 2) * 128 + i] = q4.z;  ks[(d4 + 2) * 128 + i] = k4.z;
        qv[(d4 + 3) * 128 + i] = q4.w;  ks[(d4 + 3) * 128 + i] = k4.w;
        *(float4*)&vv[i * 64 + d4] = v4;
    }
    __syncthreads();

    const int tx = tid & 15, ty = tid >> 4;
    const int ib = tx * 8, jb = ty * 8;
    float accS[8][8];
#pragma unroll
    for (int r = 0; r < 8; r++)
#pragma unroll
        for (int c = 0; c < 8; c++) accS[r][c] = 0.f;

#pragma unroll 4
    for (int d = 0; d < 64; d++) {
        float qr[8], kr[8];
        *(float4*)&qr[0] = *(const float4*)&qv[d * 128 + ib];
        *(float4*)&qr[4] = *(const float4*)&qv[d * 128 + ib + 4];
        *(float4*)&kr[0] = *(const float4*)&ks[d * 128 + jb];
        *(float4*)&kr[4] = *(const float4*)&ks[d * 128 + jb + 4];
#pragma unroll
        for (int r = 0; r < 8; r++)
#pragma unroll
            for (int c = 0; c < 8; c++)
                accS[r][c] = fmaf(qr[r], kr[c], accS[r][c]);
    }
    __syncthreads();   // q/k reads done; safe to overwrite with Est

    // E' = exp(s/8)-1 (causal-in-block), transposed Est[j][i], LD=128
#pragma unroll
    for (int c = 0; c < 8; c++) {
        const int j = jb + c;
        float e[8];
#pragma unroll
        for (int r = 0; r < 8; r++) {
            const int i = ib + r;
            e[r] = (j <= i) ? (expf(accS[r][c] * 0.125f) - 1.0f) : 0.0f;
        }
        *(float4*)&Est[j * 128 + ib]     = make_float4(e[0], e[1], e[2], e[3]);
        *(float4*)&Est[j * 128 + ib + 4] = make_float4(e[4], e[5], e[6], e[7]);
    }
    __syncthreads();

    if (tid < 128) {
        float s = 0.f;
#pragma unroll 4
        for (int j = 0; j < 128; j++) s += Est[j * 128 + tid];
        rowinv[tid] = 1.0f / (s + 4096.0f);
    }
    __syncthreads();

    const int i0 = ty * 8, d0 = tx * 4;
    float accO[8][4];
#pragma unroll
    for (int r = 0; r < 8; r++)
#pragma unroll
        for (int c = 0; c < 4; c++) accO[r][c] = 0.f;

#pragma unroll 2
    for (int j = 0; j < 128; j++) {
        float er[8];
        *(float4*)&er[0] = *(const float4*)&Est[j * 128 + i0];
        *(float4*)&er[4] = *(const float4*)&Est[j * 128 + i0 + 4];
        float4 v4 = *(const float4*)&vv[j * 64 + d0];
#pragma unroll
        for (int r = 0; r < 8; r++) {
            accO[r][0] = fmaf(er[r], v4.x, accO[r][0]);
            accO[r][1] = fmaf(er[r], v4.y, accO[r][1]);
            accO[r][2] = fmaf(er[r], v4.z, accO[r][2]);
            accO[r][3] = fmaf(er[r], v4.w, accO[r][3]);
        }
    }

    const float4 sv4 = *(const float4*)&g_sv[coff + d0];
#pragma unroll
    for (int r = 0; r < 8; r++) {
        const int i = i0 + r;
        const float riv = rowinv[i];
        float4 o;
        o.x = (accO[r][0] + sv4.x) * riv;
        o.y = (accO[r][1] + sv4.y) * riv;
        o.z = (accO[r][2] + sv4.z) * riv;
        o.w = (accO[r][3] + sv4.w) * riv;
        __nv_bfloat16 hx = __float2bfloat16(o.x), hy = __float2bfloat16(o.y);
        __nv_bfloat16 hz = __float2bfloat16(o.z), hw = __float2bfloat16(o.w);
        const int base = ((t0 + i) * E_DIM + coff + d0) >> 1;
        __nv_bfloat162* H = (__nv_bfloat162*)g_ahi;
        __nv_bfloat162* L = (__nv_bfloat162*)g_alo;
        H[base + 0] = __nv_bfloat162{hx, hy};
        H[base + 1] = __nv_bfloat162{hz, hw};
        L[base + 0] = __nv_bfloat162{__float2bfloat16(o.x - __bfloat162float(hx)),
                                     __float2bfloat16(o.y - __bfloat162float(hy))};
        L[base + 1] = __nv_bfloat162{__float2bfloat16(o.z - __bfloat162float(hz)),
                                     __float2bfloat16(o.w - __bfloat162float(hw))};
    }
}

// ---------------- CEMA: chunked linear scan ----------------
__global__ void __launch_bounds__(128)
cema_pass1(const float* __restrict__ x, const float* __restrict__ p_coeff,
           const float* __restrict__ q_coeff, const float* __restrict__ gamma)
{
    const int gid  = blockIdx.x * 128 + threadIdx.x;
    const int e    = gid & 511;
    const int chnk = gid >> 9;
    float p[NDIMS], q[NDIMS], g[NDIMS], h[NDIMS];
#pragma unroll
    for (int d = 0; d < NDIMS; d++) {
        p[d] = p_coeff[e * NDIMS + d];
        q[d] = q_coeff[e * NDIMS + d];
        g[d] = gamma  [e * NDIMS + d];
        h[d] = 0.f;
    }
    const int tbase = chnk * 128;
    for (int t = 0; t < 128; t++) {
        const float xv = x[(tbase + t) * E_DIM + e];
        float y = 0.f;
#pragma unroll
        for (int d = 0; d < NDIMS; d++) {
            h[d] = fmaf(q[d], h[d], p[d] * xv);
            y    = fmaf(g[d], h[d], y);
        }
        g_cema[(tbase + t) * E_DIM + e] = y;
    }
#pragma unroll
    for (int d = 0; d < NDIMS; d++)
        g_hend[chnk * (E_DIM * NDIMS) + e * NDIMS + d] = h[d];
}

__global__ void __launch_bounds__(128)
cema_carry(const float* __restrict__ q_coeff)
{
    const int gid = blockIdx.x * 128 + threadIdx.x;
    const float q = q_coeff[gid];
    float q128 = q;
#pragma unroll
    for (int i = 0; i < 7; i++) q128 *= q128;
    float G = 0.f;
    for (int c = 0; c < CHUNKS; c++) {
        g_carry[c * (E_DIM * NDIMS) + gid] = G;
        G = fmaf(q128, G, g_hend[c * (E_DIM * NDIMS) + gid]);
    }
}

__global__ void __launch_bounds__(128)
cema_pass2(const float* __restrict__ q_coeff, const float* __restrict__ gamma)
{
    const int gid  = blockIdx.x * 128 + threadIdx.x;
    const int e    = gid & 511;
    const int chnk = gid >> 9;
    if (chnk == 0) return;
    float q[NDIMS], w[NDIMS];
#pragma unroll
    for (int d = 0; d < NDIMS; d++) {
        q[d] = q_coeff[e * NDIMS + d];
        w[d] = gamma[e * NDIMS + d] * g_carry[chnk * (E_DIM * NDIMS) + e * NDIMS + d];
    }
    const int tbase = chnk * 128;
    for (int t = 0; t < 128; t++) {
        float y = 0.f;
#pragma unroll
        for (int d = 0; d < NDIMS; d++) {
            w[d] *= q[d];
            y    += w[d];
        }
        g_cema[(tbase + t) * E_DIM + e] += y;
    }
}

// ---------------------------- launch ----------------------------
extern "C" void kernel_launch(void* const* d_in, const int* in_sizes, int n_in,
                              void* d_out, int out_size)
{
    (void)in_sizes; (void)n_in; (void)out_size;
    const float* x       = (const float*)d_in[0];
    const float* W_qkv   = (const float*)d_in[1];
    const float* b_qkv   = (const float*)d_in[2];
    const float* W_out   = (const float*)d_in[3];
    const float* b_out   = (const float*)d_in[4];
    const float* p_coeff = (const float*)d_in[6];
    const float* q_coeff = (const float*)d_in[7];
    const float* gamma   = (const float*)d_in[8];
    const float* aw      = (const float*)d_in[9];
    float* out = (float*)d_out;

    float *qkvp = nullptr, *cemap = nullptr;
    __nv_bfloat16 *xhi, *xlo, *ahi, *alo, *wqh, *wql, *woh, *wol;
    cudaGetSymbolAddress((void**)&qkvp,  g_qkv);
    cudaGetSymbolAddress((void**)&cemap, g_cema);
    cudaGetSymbolAddress((void**)&xhi, g_xhi);
    cudaGetSymbolAddress((void**)&xlo, g_xlo);
    cudaGetSymbolAddress((void**)&ahi, g_ahi);
    cudaGetSymbolAddress((void**)&alo, g_alo);
    cudaGetSymbolAddress((void**)&wqh, g_wqT_hi);
    cudaGetSymbolAddress((void**)&wql, g_wqT_lo);
    cudaGetSymbolAddress((void**)&woh, g_woT_hi);
    cudaGetSymbolAddress((void**)&wol, g_woT_lo);

    cudaFuncSetAttribute(gemm_mma, cudaFuncAttributeMaxDynamicSharedMemorySize, GEMM_SMEM_BYTES);
    cudaFuncSetAttribute(attn_kernel, cudaFuncAttributeMaxDynamicSharedMemorySize,
                         ATTN_SMEM_FLOATS * (int)sizeof(float));

    // prep: bf16 hi/lo splits + weight transposes
    conv_hilo<<<(N_TOK * E_DIM / 4) / 256, 256>>>(x, xhi, xlo);
    transpose_conv<<<dim3(QKV_LD / 32, E_DIM / 32), dim3(32, 8)>>>(W_qkv, wqh, wql, E_DIM, QKV_LD);
    transpose_conv<<<dim3(E_DIM / 32, E_DIM / 32), dim3(32, 8)>>>(W_out, woh, wol, E_DIM, E_DIM);

    // QKV projection (tensor cores, bf16x3)
    gemm_mma<<<dim3(QKV_LD / 128, N_TOK / 128), 256, GEMM_SMEM_BYTES>>>(
        xhi, xlo, wqh, wql, b_qkv, qkvp, QKV_LD, 0, nullptr, nullptr);

    // per-head V sums
    sv_init_kernel<<<1, E_DIM>>>();
    sv_kernel<<<NBLK, E_DIM>>>();

    // block-local attention (writes bf16 hi/lo)
    attn_kernel<<<NH * NBLK, 256, ATTN_SMEM_FLOATS * (int)sizeof(float)>>>();

    // CEMA
    cema_pass1<<<(E_DIM * CHUNKS) / 128, 128>>>(x, p_coeff, q_coeff, gamma);
    cema_carry<<<(E_DIM * NDIMS) / 128, 128>>>(q_coeff);
    cema_pass2<<<(E_DIM * CHUNKS) / 128, 128>>>(q_coeff, gamma);

    // out projection fused with adaptive combine (tensor cores)
    gemm_mma<<<dim3(E_DIM / 128, N_TOK / 128), 256, GEMM_SMEM_BYTES>>>(
        ahi, alo, woh, wol, b_out, out, E_DIM, 1, cemap, aw);
}